// round 1
// baseline (speedup 1.0000x reference)
#include <cuda_runtime.h>

#define D_MODEL 768
#define NUM_HEADS 12
#define D_K 64
#define BATCH 2
#define SEQ 2048
#define M_ROWS (BATCH * SEQ)   // 4096

// Scratch (allocation-free rule: __device__ globals)
__device__ float g_Q[M_ROWS * D_MODEL];
__device__ float g_K[M_ROWS * D_MODEL];
__device__ float g_V[M_ROWS * D_MODEL];
__device__ float g_C[M_ROWS * D_MODEL];

// ---------------------------------------------------------------------------
// Linear: Y[M, 768] = X[M, 768] @ W^T + bias,  W stored [out=768, in=768]
// Block: 64x64 output tile, 256 threads, 4x4 per thread, BK=16.
// ---------------------------------------------------------------------------
__global__ __launch_bounds__(256) void linear_kernel(
    const float* __restrict__ X, const float* __restrict__ W,
    const float* __restrict__ bias, float* __restrict__ Y)
{
    __shared__ float As[16][65];   // As[kk][mm]
    __shared__ float Bs[16][65];   // Bs[kk][nn] = W[n][k]

    const int t  = threadIdx.x;
    const int tx = t & 15;
    const int ty = t >> 4;
    const int m0 = blockIdx.y * 64;
    const int n0 = blockIdx.x * 64;

    const int lrow = t >> 2;         // 0..63
    const int lk0  = (t & 3) * 4;    // 0,4,8,12

    float acc[4][4] = {};

    for (int k0 = 0; k0 < D_MODEL; k0 += 16) {
        #pragma unroll
        for (int i = 0; i < 4; i++) {
            As[lk0 + i][lrow] = X[(m0 + lrow) * D_MODEL + k0 + lk0 + i];
            Bs[lk0 + i][lrow] = W[(n0 + lrow) * D_MODEL + k0 + lk0 + i];
        }
        __syncthreads();
        #pragma unroll
        for (int kk = 0; kk < 16; kk++) {
            float a[4], b[4];
            #pragma unroll
            for (int i = 0; i < 4; i++) a[i] = As[kk][ty * 4 + i];
            #pragma unroll
            for (int j = 0; j < 4; j++) b[j] = Bs[kk][tx * 4 + j];
            #pragma unroll
            for (int i = 0; i < 4; i++)
                #pragma unroll
                for (int j = 0; j < 4; j++)
                    acc[i][j] += a[i] * b[j];
        }
        __syncthreads();
    }

    // Epilogue: add bias, vectorized float4 stores along n
    const int ncol = n0 + tx * 4;
    float4 bv = *reinterpret_cast<const float4*>(&bias[ncol]);
    #pragma unroll
    for (int i = 0; i < 4; i++) {
        float4 o;
        o.x = acc[i][0] + bv.x;
        o.y = acc[i][1] + bv.y;
        o.z = acc[i][2] + bv.z;
        o.w = acc[i][3] + bv.w;
        *reinterpret_cast<float4*>(&Y[(size_t)(m0 + ty * 4 + i) * D_MODEL + ncol]) = o;
    }
}

// ---------------------------------------------------------------------------
// Flash attention, non-causal. One block per (q-tile of 64, head, batch).
// 256 threads as 16x16; each thread owns 4 q-rows x (4 key-cols | 4 d-cols).
// Heads live interleaved in the [B, S, 768] layout at column offset h*64.
// ---------------------------------------------------------------------------
__global__ __launch_bounds__(256) void attn_kernel(
    const float* __restrict__ Q, const float* __restrict__ K,
    const float* __restrict__ V, float* __restrict__ C)
{
    extern __shared__ float sm[];
    float* Qs = sm;                 // [64][64]
    float* Ks = Qs + 64 * 64;       // [64][65]  (padded: rows vary across lanes)
    float* Vs = Ks + 64 * 65;       // [64][64]
    float* Ps = Vs + 64 * 64;       // [64][64]

    const int b  = blockIdx.z;
    const int h  = blockIdx.y;
    const int q0 = blockIdx.x * 64;

    const float* Qb = Q + (size_t)b * SEQ * D_MODEL + h * D_K;
    const float* Kb = K + (size_t)b * SEQ * D_MODEL + h * D_K;
    const float* Vb = V + (size_t)b * SEQ * D_MODEL + h * D_K;
    float*       Cb = C + (size_t)b * SEQ * D_MODEL + h * D_K;

    const int t  = threadIdx.x;
    const int tx = t & 15;
    const int ty = t >> 4;

    // Load Q tile (coalesced: consecutive threads -> consecutive d)
    #pragma unroll
    for (int i = 0; i < 16; i++) {
        int idx = t + i * 256;          // 0..4095
        int r = idx >> 6, c = idx & 63;
        Qs[r * 64 + c] = Qb[(size_t)(q0 + r) * D_MODEL + c];
    }

    float m_i[4], l_i[4], O[4][4] = {};
    #pragma unroll
    for (int i = 0; i < 4; i++) { m_i[i] = -1e30f; l_i[i] = 0.0f; }

    const float scale = 0.125f;  // 1/sqrt(64)

    for (int kv0 = 0; kv0 < SEQ; kv0 += 64) {
        __syncthreads();  // previous iteration's PV readers done with Vs/Ps
        #pragma unroll
        for (int i = 0; i < 16; i++) {
            int idx = t + i * 256;
            int r = idx >> 6, c = idx & 63;
            Ks[r * 65 + c] = Kb[(size_t)(kv0 + r) * D_MODEL + c];
            Vs[r * 64 + c] = Vb[(size_t)(kv0 + r) * D_MODEL + c];
        }
        __syncthreads();

        // S = (Q K^T) * scale, 4x4 register tile
        float acc[4][4] = {};
        #pragma unroll 8
        for (int d = 0; d < 64; d++) {
            float a[4], kk[4];
            #pragma unroll
            for (int i = 0; i < 4; i++) a[i]  = Qs[(ty * 4 + i) * 64 + d];
            #pragma unroll
            for (int j = 0; j < 4; j++) kk[j] = Ks[(tx * 4 + j) * 65 + d];
            #pragma unroll
            for (int i = 0; i < 4; i++)
                #pragma unroll
                for (int j = 0; j < 4; j++)
                    acc[i][j] += a[i] * kk[j];
        }

        // Online softmax per row (row owned by the 16 tx lanes of one ty group)
        #pragma unroll
        for (int i = 0; i < 4; i++) {
            float mx = acc[i][0] * scale;
            #pragma unroll
            for (int j = 1; j < 4; j++) mx = fmaxf(mx, acc[i][j] * scale);
            #pragma unroll
            for (int off = 8; off >= 1; off >>= 1)
                mx = fmaxf(mx, __shfl_xor_sync(0xffffffffu, mx, off, 16));

            float mnew  = fmaxf(m_i[i], mx);
            float alpha = __expf(m_i[i] - mnew);
            m_i[i] = mnew;

            float rs = 0.0f;
            #pragma unroll
            for (int j = 0; j < 4; j++) {
                float p = __expf(acc[i][j] * scale - mnew);
                acc[i][j] = p;
                rs += p;
            }
            #pragma unroll
            for (int off = 8; off >= 1; off >>= 1)
                rs += __shfl_xor_sync(0xffffffffu, rs, off, 16);

            l_i[i] = l_i[i] * alpha + rs;
            #pragma unroll
            for (int j = 0; j < 4; j++) O[i][j] *= alpha;
        }

        // Stage P to smem for the PV GEMM
        #pragma unroll
        for (int i = 0; i < 4; i++)
            #pragma unroll
            for (int j = 0; j < 4; j++)
                Ps[(ty * 4 + i) * 64 + tx * 4 + j] = acc[i][j];
        __syncthreads();

        // O += P @ V   (thread owns rows ty*4.. , d-cols tx*4..)
        #pragma unroll 8
        for (int c = 0; c < 64; c++) {
            float a[4], vv[4];
            #pragma unroll
            for (int i = 0; i < 4; i++) a[i]  = Ps[(ty * 4 + i) * 64 + c];
            #pragma unroll
            for (int j = 0; j < 4; j++) vv[j] = Vs[c * 64 + tx * 4 + j];
            #pragma unroll
            for (int i = 0; i < 4; i++)
                #pragma unroll
                for (int j = 0; j < 4; j++)
                    O[i][j] += a[i] * vv[j];
        }
    }

    // Epilogue: normalize and store (float4 along d)
    #pragma unroll
    for (int i = 0; i < 4; i++) {
        float inv = 1.0f / l_i[i];
        float4 o;
        o.x = O[i][0] * inv;
        o.y = O[i][1] * inv;
        o.z = O[i][2] * inv;
        o.w = O[i][3] * inv;
        *reinterpret_cast<float4*>(
            &Cb[(size_t)(q0 + ty * 4 + i) * D_MODEL + tx * 4]) = o;
    }
}

// ---------------------------------------------------------------------------
// Launch
// ---------------------------------------------------------------------------
extern "C" void kernel_launch(void* const* d_in, const int* in_sizes, int n_in,
                              void* d_out, int out_size)
{
    const float* q   = (const float*)d_in[0];
    const float* k   = (const float*)d_in[1];
    const float* v   = (const float*)d_in[2];
    const float* w_q = (const float*)d_in[3];
    const float* b_q = (const float*)d_in[4];
    const float* w_k = (const float*)d_in[5];
    const float* b_k = (const float*)d_in[6];
    const float* w_v = (const float*)d_in[7];
    const float* b_v = (const float*)d_in[8];
    const float* w_o = (const float*)d_in[9];
    const float* b_o = (const float*)d_in[10];
    float* out = (float*)d_out;

    float *gQ, *gK, *gV, *gC;
    cudaGetSymbolAddress((void**)&gQ, g_Q);
    cudaGetSymbolAddress((void**)&gK, g_K);
    cudaGetSymbolAddress((void**)&gV, g_V);
    cudaGetSymbolAddress((void**)&gC, g_C);

    const int attn_smem = (64 * 64 * 3 + 64 * 65) * sizeof(float);  // 65792 B
    cudaFuncSetAttribute(attn_kernel,
                         cudaFuncAttributeMaxDynamicSharedMemorySize, attn_smem);

    dim3 lin_grid(D_MODEL / 64, M_ROWS / 64);  // (12, 64)
    linear_kernel<<<lin_grid, 256>>>(q, w_q, b_q, gQ);
    linear_kernel<<<lin_grid, 256>>>(k, w_k, b_k, gK);
    linear_kernel<<<lin_grid, 256>>>(v, w_v, b_v, gV);

    dim3 attn_grid(SEQ / 64, NUM_HEADS, BATCH);  // (32, 12, 2)
    attn_kernel<<<attn_grid, 256, attn_smem>>>(gQ, gK, gV, gC);

    linear_kernel<<<lin_grid, 256>>>(gC, w_o, b_o, out);
}

// round 2
// speedup vs baseline: 1.0023x; 1.0023x over previous
#include <cuda_runtime.h>

#define D_MODEL 768
#define NUM_HEADS 12
#define D_K 64
#define BATCH 2
#define SEQ 2048
#define M_ROWS (BATCH * SEQ)   // 4096

// Scratch (allocation-free rule: __device__ globals)
__device__ float g_Q[M_ROWS * D_MODEL];
__device__ float g_K[M_ROWS * D_MODEL];
__device__ float g_V[M_ROWS * D_MODEL];
__device__ float g_C[M_ROWS * D_MODEL];

// ---------------------------------------------------------------------------
// Linear: Y[M, 768] = X[M, 768] @ W^T + bias,  W stored [out=768, in=768]
// Block: 64x64 output tile, 256 threads, 4x4 per thread, BK=16.
// ---------------------------------------------------------------------------
__global__ __launch_bounds__(256) void linear_kernel(
    const float* __restrict__ X, const float* __restrict__ W,
    const float* __restrict__ bias, float* __restrict__ Y)
{
    __shared__ float As[16][65];   // As[kk][mm]
    __shared__ float Bs[16][65];   // Bs[kk][nn] = W[n][k]

    const int t  = threadIdx.x;
    const int tx = t & 15;
    const int ty = t >> 4;
    const int m0 = blockIdx.y * 64;
    const int n0 = blockIdx.x * 64;

    const int lrow = t >> 2;         // 0..63
    const int lk0  = (t & 3) * 4;    // 0,4,8,12

    float acc[4][4] = {};

    for (int k0 = 0; k0 < D_MODEL; k0 += 16) {
        #pragma unroll
        for (int i = 0; i < 4; i++) {
            As[lk0 + i][lrow] = X[(m0 + lrow) * D_MODEL + k0 + lk0 + i];
            Bs[lk0 + i][lrow] = W[(n0 + lrow) * D_MODEL + k0 + lk0 + i];
        }
        __syncthreads();
        #pragma unroll
        for (int kk = 0; kk < 16; kk++) {
            float a[4], b[4];
            #pragma unroll
            for (int i = 0; i < 4; i++) a[i] = As[kk][ty * 4 + i];
            #pragma unroll
            for (int j = 0; j < 4; j++) b[j] = Bs[kk][tx * 4 + j];
            #pragma unroll
            for (int i = 0; i < 4; i++)
                #pragma unroll
                for (int j = 0; j < 4; j++)
                    acc[i][j] += a[i] * b[j];
        }
        __syncthreads();
    }

    // Epilogue: add bias, vectorized float4 stores along n
    const int ncol = n0 + tx * 4;
    float4 bv = *reinterpret_cast<const float4*>(&bias[ncol]);
    #pragma unroll
    for (int i = 0; i < 4; i++) {
        float4 o;
        o.x = acc[i][0] + bv.x;
        o.y = acc[i][1] + bv.y;
        o.z = acc[i][2] + bv.z;
        o.w = acc[i][3] + bv.w;
        *reinterpret_cast<float4*>(&Y[(size_t)(m0 + ty * 4 + i) * D_MODEL + ncol]) = o;
    }
}

// ---------------------------------------------------------------------------
// Flash attention, non-causal. One block per (q-tile of 64, head, batch).
// 256 threads as 16x16; each thread owns 4 q-rows x (4 key-cols | 4 d-cols).
// Heads live interleaved in the [B, S, 768] layout at column offset h*64.
// ---------------------------------------------------------------------------
__global__ __launch_bounds__(256) void attn_kernel(
    const float* __restrict__ Q, const float* __restrict__ K,
    const float* __restrict__ V, float* __restrict__ C)
{
    extern __shared__ float sm[];
    float* Qs = sm;                 // [64][64]
    float* Ks = Qs + 64 * 64;       // [64][65]  (padded: rows vary across lanes)
    float* Vs = Ks + 64 * 65;       // [64][64]
    float* Ps = Vs + 64 * 64;       // [64][64]

    const int b  = blockIdx.z;
    const int h  = blockIdx.y;
    const int q0 = blockIdx.x * 64;

    const float* Qb = Q + (size_t)b * SEQ * D_MODEL + h * D_K;
    const float* Kb = K + (size_t)b * SEQ * D_MODEL + h * D_K;
    const float* Vb = V + (size_t)b * SEQ * D_MODEL + h * D_K;
    float*       Cb = C + (size_t)b * SEQ * D_MODEL + h * D_K;

    const int t  = threadIdx.x;
    const int tx = t & 15;
    const int ty = t >> 4;

    // Load Q tile (coalesced: consecutive threads -> consecutive d)
    #pragma unroll
    for (int i = 0; i < 16; i++) {
        int idx = t + i * 256;          // 0..4095
        int r = idx >> 6, c = idx & 63;
        Qs[r * 64 + c] = Qb[(size_t)(q0 + r) * D_MODEL + c];
    }

    float m_i[4], l_i[4], O[4][4] = {};
    #pragma unroll
    for (int i = 0; i < 4; i++) { m_i[i] = -1e30f; l_i[i] = 0.0f; }

    const float scale = 0.125f;  // 1/sqrt(64)

    for (int kv0 = 0; kv0 < SEQ; kv0 += 64) {
        __syncthreads();  // previous iteration's PV readers done with Vs/Ps
        #pragma unroll
        for (int i = 0; i < 16; i++) {
            int idx = t + i * 256;
            int r = idx >> 6, c = idx & 63;
            Ks[r * 65 + c] = Kb[(size_t)(kv0 + r) * D_MODEL + c];
            Vs[r * 64 + c] = Vb[(size_t)(kv0 + r) * D_MODEL + c];
        }
        __syncthreads();

        // S = (Q K^T) * scale, 4x4 register tile
        float acc[4][4] = {};
        #pragma unroll 8
        for (int d = 0; d < 64; d++) {
            float a[4], kk[4];
            #pragma unroll
            for (int i = 0; i < 4; i++) a[i]  = Qs[(ty * 4 + i) * 64 + d];
            #pragma unroll
            for (int j = 0; j < 4; j++) kk[j] = Ks[(tx * 4 + j) * 65 + d];
            #pragma unroll
            for (int i = 0; i < 4; i++)
                #pragma unroll
                for (int j = 0; j < 4; j++)
                    acc[i][j] += a[i] * kk[j];
        }

        // Online softmax per row (row owned by the 16 tx lanes of one ty group)
        #pragma unroll
        for (int i = 0; i < 4; i++) {
            float mx = acc[i][0] * scale;
            #pragma unroll
            for (int j = 1; j < 4; j++) mx = fmaxf(mx, acc[i][j] * scale);
            #pragma unroll
            for (int off = 8; off >= 1; off >>= 1)
                mx = fmaxf(mx, __shfl_xor_sync(0xffffffffu, mx, off, 16));

            float mnew  = fmaxf(m_i[i], mx);
            float alpha = __expf(m_i[i] - mnew);
            m_i[i] = mnew;

            float rs = 0.0f;
            #pragma unroll
            for (int j = 0; j < 4; j++) {
                float p = __expf(acc[i][j] * scale - mnew);
                acc[i][j] = p;
                rs += p;
            }
            #pragma unroll
            for (int off = 8; off >= 1; off >>= 1)
                rs += __shfl_xor_sync(0xffffffffu, rs, off, 16);

            l_i[i] = l_i[i] * alpha + rs;
            #pragma unroll
            for (int j = 0; j < 4; j++) O[i][j] *= alpha;
        }

        // Stage P to smem for the PV GEMM
        #pragma unroll
        for (int i = 0; i < 4; i++)
            #pragma unroll
            for (int j = 0; j < 4; j++)
                Ps[(ty * 4 + i) * 64 + tx * 4 + j] = acc[i][j];
        __syncthreads();

        // O += P @ V   (thread owns rows ty*4.. , d-cols tx*4..)
        #pragma unroll 8
        for (int c = 0; c < 64; c++) {
            float a[4], vv[4];
            #pragma unroll
            for (int i = 0; i < 4; i++) a[i]  = Ps[(ty * 4 + i) * 64 + c];
            #pragma unroll
            for (int j = 0; j < 4; j++) vv[j] = Vs[c * 64 + tx * 4 + j];
            #pragma unroll
            for (int i = 0; i < 4; i++)
                #pragma unroll
                for (int j = 0; j < 4; j++)
                    O[i][j] += a[i] * vv[j];
        }
    }

    // Epilogue: normalize and store (float4 along d)
    #pragma unroll
    for (int i = 0; i < 4; i++) {
        float inv = 1.0f / l_i[i];
        float4 o;
        o.x = O[i][0] * inv;
        o.y = O[i][1] * inv;
        o.z = O[i][2] * inv;
        o.w = O[i][3] * inv;
        *reinterpret_cast<float4*>(
            &Cb[(size_t)(q0 + ty * 4 + i) * D_MODEL + tx * 4]) = o;
    }
}

// ---------------------------------------------------------------------------
// Launch
// ---------------------------------------------------------------------------
extern "C" void kernel_launch(void* const* d_in, const int* in_sizes, int n_in,
                              void* d_out, int out_size)
{
    const float* q   = (const float*)d_in[0];
    const float* k   = (const float*)d_in[1];
    const float* v   = (const float*)d_in[2];
    const float* w_q = (const float*)d_in[3];
    const float* b_q = (const float*)d_in[4];
    const float* w_k = (const float*)d_in[5];
    const float* b_k = (const float*)d_in[6];
    const float* w_v = (const float*)d_in[7];
    const float* b_v = (const float*)d_in[8];
    const float* w_o = (const float*)d_in[9];
    const float* b_o = (const float*)d_in[10];
    float* out = (float*)d_out;

    float *gQ, *gK, *gV, *gC;
    cudaGetSymbolAddress((void**)&gQ, g_Q);
    cudaGetSymbolAddress((void**)&gK, g_K);
    cudaGetSymbolAddress((void**)&gV, g_V);
    cudaGetSymbolAddress((void**)&gC, g_C);

    const int attn_smem = (64 * 64 * 3 + 64 * 65) * sizeof(float);  // 65792 B
    cudaFuncSetAttribute(attn_kernel,
                         cudaFuncAttributeMaxDynamicSharedMemorySize, attn_smem);

    dim3 lin_grid(D_MODEL / 64, M_ROWS / 64);  // (12, 64)
    linear_kernel<<<lin_grid, 256>>>(q, w_q, b_q, gQ);
    linear_kernel<<<lin_grid, 256>>>(k, w_k, b_k, gK);
    linear_kernel<<<lin_grid, 256>>>(v, w_v, b_v, gV);

    dim3 attn_grid(SEQ / 64, NUM_HEADS, BATCH);  // (32, 12, 2)
    attn_kernel<<<attn_grid, 256, attn_smem>>>(gQ, gK, gV, gC);

    linear_kernel<<<lin_grid, 256>>>(gC, w_o, b_o, out);
}

// round 4
// speedup vs baseline: 1.6432x; 1.6395x over previous
#include <cuda_runtime.h>
#include <cuda_bf16.h>
#include <cstdint>

#define D_MODEL 768
#define NUM_HEADS 12
#define D_K 64
#define BATCH 2
#define SEQ 2048
#define M_ROWS (BATCH * SEQ)   // 4096

// ---------------------------------------------------------------------------
// Scratch (__device__ globals; allocation-free rule)
// ---------------------------------------------------------------------------
__device__ float g_Q[M_ROWS * D_MODEL];
__device__ float g_K[M_ROWS * D_MODEL];
__device__ float g_V[M_ROWS * D_MODEL];
__device__ float g_C[M_ROWS * D_MODEL];
__device__ __nv_bfloat16 g_xh[M_ROWS * D_MODEL];
__device__ __nv_bfloat16 g_xl[M_ROWS * D_MODEL];
__device__ __nv_bfloat16 g_wh[D_MODEL * D_MODEL];
__device__ __nv_bfloat16 g_wl[D_MODEL * D_MODEL];

// ---------------------------------------------------------------------------
// PTX helpers (family-target safe: cp.async / ldmatrix / mma.sync only)
// ---------------------------------------------------------------------------
__device__ __forceinline__ uint32_t smem_to_u32(const void* p) {
    uint32_t a;
    asm("{ .reg .u64 t; cvta.to.shared.u64 t, %1; cvt.u32.u64 %0, t; }"
        : "=r"(a) : "l"(p));
    return a;
}

__device__ __forceinline__ void cp_async16(uint32_t dst, const void* src) {
    asm volatile("cp.async.cg.shared.global [%0], [%1], 16;" :: "r"(dst), "l"(src));
}
__device__ __forceinline__ void cp_commit() {
    asm volatile("cp.async.commit_group;" ::: "memory");
}
template <int N>
__device__ __forceinline__ void cp_wait_group() {
    asm volatile("cp.async.wait_group %0;" :: "n"(N) : "memory");
}

__device__ __forceinline__ void ldsm4(uint32_t& r0, uint32_t& r1, uint32_t& r2,
                                      uint32_t& r3, uint32_t addr) {
    asm volatile("ldmatrix.sync.aligned.m8n8.x4.shared.b16 {%0,%1,%2,%3}, [%4];"
                 : "=r"(r0), "=r"(r1), "=r"(r2), "=r"(r3) : "r"(addr));
}

__device__ __forceinline__ void mma16816(float* d, const uint32_t* a, const uint32_t* b) {
    asm volatile(
        "mma.sync.aligned.m16n8k16.row.col.f32.bf16.bf16.f32 "
        "{%0,%1,%2,%3}, {%4,%5,%6,%7}, {%8,%9}, {%0,%1,%2,%3};"
        : "+f"(d[0]), "+f"(d[1]), "+f"(d[2]), "+f"(d[3])
        : "r"(a[0]), "r"(a[1]), "r"(a[2]), "r"(a[3]), "r"(b[0]), "r"(b[1]));
}

// ---------------------------------------------------------------------------
// Split fp32 -> (bf16 hi, bf16 lo)
// ---------------------------------------------------------------------------
__global__ __launch_bounds__(256) void split_kernel(
    const float* __restrict__ x, __nv_bfloat16* __restrict__ hi,
    __nv_bfloat16* __restrict__ lo, int n)
{
    int i = (blockIdx.x * 256 + threadIdx.x) * 4;
    if (i >= n) return;
    float4 v = *reinterpret_cast<const float4*>(x + i);
    float vs[4] = {v.x, v.y, v.z, v.w};
    uint32_t hp[2], lp[2];
    #pragma unroll
    for (int p = 0; p < 2; p++) {
        __nv_bfloat16 h0 = __float2bfloat16(vs[p * 2 + 0]);
        __nv_bfloat16 h1 = __float2bfloat16(vs[p * 2 + 1]);
        __nv_bfloat16 l0 = __float2bfloat16(vs[p * 2 + 0] - __bfloat162float(h0));
        __nv_bfloat16 l1 = __float2bfloat16(vs[p * 2 + 1] - __bfloat162float(h1));
        hp[p] = (uint32_t)__bfloat16_as_ushort(h0) | ((uint32_t)__bfloat16_as_ushort(h1) << 16);
        lp[p] = (uint32_t)__bfloat16_as_ushort(l0) | ((uint32_t)__bfloat16_as_ushort(l1) << 16);
    }
    *reinterpret_cast<uint2*>(hi + i) = make_uint2(hp[0], hp[1]);
    *reinterpret_cast<uint2*>(lo + i) = make_uint2(lp[0], lp[1]);
}

// ---------------------------------------------------------------------------
// mma.sync GEMM: Y[.,768] = Ah@Bh^T + Ah@Bl^T + Al@Bh^T + bias
// CTA tile 128x128, 8 warps (2x4), warp tile 64x32, BK=32, 3-stage cp.async.
// SMEM per stage: A[128][32] bf16 pad->80B rows (10240B) + B same. 61440B total.
// ---------------------------------------------------------------------------
#define BK 32
#define SMEM_STRIDE 80                     // 32 bf16 = 64B + 16B pad
#define A_STAGE_BYTES (128 * SMEM_STRIDE)  // 10240
#define STAGE_BYTES (2 * A_STAGE_BYTES)    // 20480
#define GEMM_SMEM (3 * STAGE_BYTES)        // 61440
#define CHUNKS_PER_PASS (D_MODEL / BK)     // 24
#define NCHUNK (3 * CHUNKS_PER_PASS)       // 72

__global__ __launch_bounds__(256) void gemm_mma(
    const __nv_bfloat16* __restrict__ Ah, const __nv_bfloat16* __restrict__ Al,
    const __nv_bfloat16* __restrict__ Bh, const __nv_bfloat16* __restrict__ Bl,
    const float* __restrict__ bias, float* __restrict__ Y)
{
    extern __shared__ __align__(128) char smem[];
    const uint32_t sb = smem_to_u32(smem);
    const int t    = threadIdx.x;
    const int wid  = t >> 5;
    const int lane = t & 31;
    const int warp_m = wid & 1;            // 0..1 -> m offset 0/64
    const int warp_n = wid >> 1;           // 0..3 -> n offset 0/32/64/96
    const int n0 = blockIdx.x * 128;
    const int m0 = blockIdx.y * 128;

    // ldmatrix per-lane offsets (bytes, within a stage)
    const uint32_t a_off = (uint32_t)(warp_m * 64 + (lane & 15)) * SMEM_STRIDE
                         + (uint32_t)(lane >> 4) * 16;
    const uint32_t b_off = (uint32_t)(warp_n * 32 + (lane & 7) + ((lane >> 4) << 3)) * SMEM_STRIDE
                         + (uint32_t)((lane >> 3) & 1) * 16;

    float acc[4][4][4] = {};  // [mt][nt][reg]

    auto load_chunk = [&](int c, int s) {
        const int pass = c / CHUNKS_PER_PASS;
        const int k0 = (c % CHUNKS_PER_PASS) * BK;
        const __nv_bfloat16* a_src = (pass == 2) ? Al : Ah;
        const __nv_bfloat16* b_src = (pass == 1) ? Bl : Bh;
        const uint32_t sA = sb + s * STAGE_BYTES;
        const uint32_t sB = sA + A_STAGE_BYTES;
        #pragma unroll
        for (int i = 0; i < 2; i++) {
            int e = t + i * 256;           // 0..511
            int row = e >> 2, seg = e & 3;
            uint32_t d = (uint32_t)(row * SMEM_STRIDE + seg * 16);
            cp_async16(sA + d, a_src + (size_t)(m0 + row) * D_MODEL + k0 + seg * 8);
            cp_async16(sB + d, b_src + (size_t)(n0 + row) * D_MODEL + k0 + seg * 8);
        }
        cp_commit();
    };

    load_chunk(0, 0);
    load_chunk(1, 1);

    for (int c = 0; c < NCHUNK; c++) {
        if (c + 1 < NCHUNK) cp_wait_group<1>(); else cp_wait_group<0>();
        __syncthreads();
        if (c + 2 < NCHUNK) load_chunk(c + 2, (c + 2) % 3);

        const uint32_t sA = sb + (c % 3) * STAGE_BYTES;
        const uint32_t sB = sA + A_STAGE_BYTES;

        #pragma unroll
        for (int ks = 0; ks < 2; ks++) {
            uint32_t af[4][4];
            #pragma unroll
            for (int mt = 0; mt < 4; mt++)
                ldsm4(af[mt][0], af[mt][1], af[mt][2], af[mt][3],
                      sA + a_off + mt * 16 * SMEM_STRIDE + ks * 32);
            uint32_t bf[4][2];
            #pragma unroll
            for (int p = 0; p < 2; p++) {
                uint32_t r0, r1, r2, r3;
                ldsm4(r0, r1, r2, r3,
                      sB + b_off + p * 16 * SMEM_STRIDE + ks * 32);
                bf[p * 2 + 0][0] = r0; bf[p * 2 + 0][1] = r1;
                bf[p * 2 + 1][0] = r2; bf[p * 2 + 1][1] = r3;
            }
            #pragma unroll
            for (int mt = 0; mt < 4; mt++)
                #pragma unroll
                for (int nt = 0; nt < 4; nt++)
                    mma16816(acc[mt][nt], af[mt], bf[nt]);
        }
        __syncthreads();
    }

    // Epilogue: d0,d1 -> (row, col..col+1); d2,d3 -> (row+8, ...)
    const int colb = n0 + warp_n * 32 + (lane & 3) * 2;
    const int rowb = m0 + warp_m * 64 + (lane >> 2);
    #pragma unroll
    for (int nt = 0; nt < 4; nt++) {
        const int col = colb + nt * 8;
        const float2 bv = *reinterpret_cast<const float2*>(&bias[col]);
        #pragma unroll
        for (int mt = 0; mt < 4; mt++) {
            const int r0 = rowb + mt * 16;
            float2 o0, o1;
            o0.x = acc[mt][nt][0] + bv.x;
            o0.y = acc[mt][nt][1] + bv.y;
            o1.x = acc[mt][nt][2] + bv.x;
            o1.y = acc[mt][nt][3] + bv.y;
            *reinterpret_cast<float2*>(&Y[(size_t)r0 * D_MODEL + col]) = o0;
            *reinterpret_cast<float2*>(&Y[(size_t)(r0 + 8) * D_MODEL + col]) = o1;
        }
    }
}

// ---------------------------------------------------------------------------
// Flash attention (known-good fp32 from R1)
// ---------------------------------------------------------------------------
__global__ __launch_bounds__(256) void attn_kernel(
    const float* __restrict__ Q, const float* __restrict__ K,
    const float* __restrict__ V, float* __restrict__ C)
{
    extern __shared__ float sm[];
    float* Qs = sm;
    float* Ks = Qs + 64 * 64;
    float* Vs = Ks + 64 * 65;
    float* Ps = Vs + 64 * 64;

    const int b  = blockIdx.z;
    const int h  = blockIdx.y;
    const int q0 = blockIdx.x * 64;

    const float* Qb = Q + (size_t)b * SEQ * D_MODEL + h * D_K;
    const float* Kb = K + (size_t)b * SEQ * D_MODEL + h * D_K;
    const float* Vb = V + (size_t)b * SEQ * D_MODEL + h * D_K;
    float*       Cb = C + (size_t)b * SEQ * D_MODEL + h * D_K;

    const int t  = threadIdx.x;
    const int tx = t & 15;
    const int ty = t >> 4;

    #pragma unroll
    for (int i = 0; i < 16; i++) {
        int idx = t + i * 256;
        int r = idx >> 6, c = idx & 63;
        Qs[r * 64 + c] = Qb[(size_t)(q0 + r) * D_MODEL + c];
    }

    float m_i[4], l_i[4], O[4][4] = {};
    #pragma unroll
    for (int i = 0; i < 4; i++) { m_i[i] = -1e30f; l_i[i] = 0.0f; }

    const float scale = 0.125f;

    for (int kv0 = 0; kv0 < SEQ; kv0 += 64) {
        __syncthreads();
        #pragma unroll
        for (int i = 0; i < 16; i++) {
            int idx = t + i * 256;
            int r = idx >> 6, c = idx & 63;
            Ks[r * 65 + c] = Kb[(size_t)(kv0 + r) * D_MODEL + c];
            Vs[r * 64 + c] = Vb[(size_t)(kv0 + r) * D_MODEL + c];
        }
        __syncthreads();

        float acc[4][4] = {};
        #pragma unroll 8
        for (int d = 0; d < 64; d++) {
            float a[4], kk[4];
            #pragma unroll
            for (int i = 0; i < 4; i++) a[i]  = Qs[(ty * 4 + i) * 64 + d];
            #pragma unroll
            for (int j = 0; j < 4; j++) kk[j] = Ks[(tx * 4 + j) * 65 + d];
            #pragma unroll
            for (int i = 0; i < 4; i++)
                #pragma unroll
                for (int j = 0; j < 4; j++)
                    acc[i][j] += a[i] * kk[j];
        }

        #pragma unroll
        for (int i = 0; i < 4; i++) {
            float mx = acc[i][0] * scale;
            #pragma unroll
            for (int j = 1; j < 4; j++) mx = fmaxf(mx, acc[i][j] * scale);
            #pragma unroll
            for (int off = 8; off >= 1; off >>= 1)
                mx = fmaxf(mx, __shfl_xor_sync(0xffffffffu, mx, off, 16));

            float mnew  = fmaxf(m_i[i], mx);
            float alpha = __expf(m_i[i] - mnew);
            m_i[i] = mnew;

            float rs = 0.0f;
            #pragma unroll
            for (int j = 0; j < 4; j++) {
                float p = __expf(acc[i][j] * scale - mnew);
                acc[i][j] = p;
                rs += p;
            }
            #pragma unroll
            for (int off = 8; off >= 1; off >>= 1)
                rs += __shfl_xor_sync(0xffffffffu, rs, off, 16);

            l_i[i] = l_i[i] * alpha + rs;
            #pragma unroll
            for (int j = 0; j < 4; j++) O[i][j] *= alpha;
        }

        #pragma unroll
        for (int i = 0; i < 4; i++)
            #pragma unroll
            for (int j = 0; j < 4; j++)
                Ps[(ty * 4 + i) * 64 + tx * 4 + j] = acc[i][j];
        __syncthreads();

        #pragma unroll 8
        for (int c = 0; c < 64; c++) {
            float a[4], vv[4];
            #pragma unroll
            for (int i = 0; i < 4; i++) a[i]  = Ps[(ty * 4 + i) * 64 + c];
            #pragma unroll
            for (int j = 0; j < 4; j++) vv[j] = Vs[c * 64 + tx * 4 + j];
            #pragma unroll
            for (int i = 0; i < 4; i++)
                #pragma unroll
                for (int j = 0; j < 4; j++)
                    O[i][j] += a[i] * vv[j];
        }
    }

    #pragma unroll
    for (int i = 0; i < 4; i++) {
        float inv = 1.0f / l_i[i];
        float4 o;
        o.x = O[i][0] * inv;
        o.y = O[i][1] * inv;
        o.z = O[i][2] * inv;
        o.w = O[i][3] * inv;
        *reinterpret_cast<float4*>(
            &Cb[(size_t)(q0 + ty * 4 + i) * D_MODEL + tx * 4]) = o;
    }
}

// ---------------------------------------------------------------------------
// Launch
// ---------------------------------------------------------------------------
extern "C" void kernel_launch(void* const* d_in, const int* in_sizes, int n_in,
                              void* d_out, int out_size)
{
    const float* q   = (const float*)d_in[0];
    const float* k   = (const float*)d_in[1];
    const float* v   = (const float*)d_in[2];
    const float* w_q = (const float*)d_in[3];
    const float* b_q = (const float*)d_in[4];
    const float* w_k = (const float*)d_in[5];
    const float* b_k = (const float*)d_in[6];
    const float* w_v = (const float*)d_in[7];
    const float* b_v = (const float*)d_in[8];
    const float* w_o = (const float*)d_in[9];
    const float* b_o = (const float*)d_in[10];
    float* out = (float*)d_out;

    float *gQ, *gK, *gV, *gC;
    cudaGetSymbolAddress((void**)&gQ, g_Q);
    cudaGetSymbolAddress((void**)&gK, g_K);
    cudaGetSymbolAddress((void**)&gV, g_V);
    cudaGetSymbolAddress((void**)&gC, g_C);
    __nv_bfloat16 *xh, *xl, *wh, *wl;
    cudaGetSymbolAddress((void**)&xh, g_xh);
    cudaGetSymbolAddress((void**)&xl, g_xl);
    cudaGetSymbolAddress((void**)&wh, g_wh);
    cudaGetSymbolAddress((void**)&wl, g_wl);

    const int attn_smem = (64 * 64 * 3 + 64 * 65) * sizeof(float);
    cudaFuncSetAttribute(attn_kernel,
                         cudaFuncAttributeMaxDynamicSharedMemorySize, attn_smem);
    cudaFuncSetAttribute(gemm_mma,
                         cudaFuncAttributeMaxDynamicSharedMemorySize, GEMM_SMEM);

    const int nx = M_ROWS * D_MODEL;
    const int nw = D_MODEL * D_MODEL;
    const int gx = nx / 4 / 256;
    const int gw = nw / 4 / 256;
    dim3 gemm_grid(D_MODEL / 128, M_ROWS / 128);  // (6, 32)

    split_kernel<<<gw, 256>>>(w_q, wh, wl, nw);
    split_kernel<<<gx, 256>>>(q, xh, xl, nx);
    gemm_mma<<<gemm_grid, 256, GEMM_SMEM>>>(xh, xl, wh, wl, b_q, gQ);

    split_kernel<<<gw, 256>>>(w_k, wh, wl, nw);
    split_kernel<<<gx, 256>>>(k, xh, xl, nx);
    gemm_mma<<<gemm_grid, 256, GEMM_SMEM>>>(xh, xl, wh, wl, b_k, gK);

    split_kernel<<<gw, 256>>>(w_v, wh, wl, nw);
    split_kernel<<<gx, 256>>>(v, xh, xl, nx);
    gemm_mma<<<gemm_grid, 256, GEMM_SMEM>>>(xh, xl, wh, wl, b_v, gV);

    dim3 attn_grid(SEQ / 64, NUM_HEADS, BATCH);
    attn_kernel<<<attn_grid, 256, attn_smem>>>(gQ, gK, gV, gC);

    split_kernel<<<gw, 256>>>(w_o, wh, wl, nw);
    split_kernel<<<gx, 256>>>(gC, xh, xl, nx);
    gemm_mma<<<gemm_grid, 256, GEMM_SMEM>>>(xh, xl, wh, wl, b_o, out);
}

// round 5
// speedup vs baseline: 3.2277x; 1.9643x over previous
#include <cuda_runtime.h>
#include <cuda_bf16.h>
#include <cstdint>

#define D_MODEL 768
#define NUM_HEADS 12
#define D_K 64
#define BATCH 2
#define SEQ 2048
#define M_ROWS (BATCH * SEQ)   // 4096

// ---------------------------------------------------------------------------
// Scratch (__device__ globals; allocation-free rule)
// ---------------------------------------------------------------------------
__device__ __nv_bfloat16 g_xh[M_ROWS * D_MODEL];
__device__ __nv_bfloat16 g_xl[M_ROWS * D_MODEL];
__device__ __nv_bfloat16 g_wh[D_MODEL * D_MODEL];
__device__ __nv_bfloat16 g_wl[D_MODEL * D_MODEL];
__device__ __nv_bfloat16 g_qh[M_ROWS * D_MODEL];
__device__ __nv_bfloat16 g_ql[M_ROWS * D_MODEL];
__device__ __nv_bfloat16 g_kh[M_ROWS * D_MODEL];
__device__ __nv_bfloat16 g_kl[M_ROWS * D_MODEL];
__device__ __nv_bfloat16 g_vh[M_ROWS * D_MODEL];
__device__ __nv_bfloat16 g_vl[M_ROWS * D_MODEL];

// ---------------------------------------------------------------------------
// PTX helpers (family-target safe: cp.async / ldmatrix / mma.sync only)
// ---------------------------------------------------------------------------
__device__ __forceinline__ uint32_t smem_to_u32(const void* p) {
    uint32_t a;
    asm("{ .reg .u64 t; cvta.to.shared.u64 t, %1; cvt.u32.u64 %0, t; }"
        : "=r"(a) : "l"(p));
    return a;
}
__device__ __forceinline__ void cp_async16(uint32_t dst, const void* src) {
    asm volatile("cp.async.cg.shared.global [%0], [%1], 16;" :: "r"(dst), "l"(src));
}
__device__ __forceinline__ void cp_commit() {
    asm volatile("cp.async.commit_group;" ::: "memory");
}
template <int N>
__device__ __forceinline__ void cp_wait_group() {
    asm volatile("cp.async.wait_group %0;" :: "n"(N) : "memory");
}
__device__ __forceinline__ void ldsm4(uint32_t& r0, uint32_t& r1, uint32_t& r2,
                                      uint32_t& r3, uint32_t addr) {
    asm volatile("ldmatrix.sync.aligned.m8n8.x4.shared.b16 {%0,%1,%2,%3}, [%4];"
                 : "=r"(r0), "=r"(r1), "=r"(r2), "=r"(r3) : "r"(addr));
}
__device__ __forceinline__ void ldsm4t(uint32_t& r0, uint32_t& r1, uint32_t& r2,
                                       uint32_t& r3, uint32_t addr) {
    asm volatile("ldmatrix.sync.aligned.m8n8.x4.trans.shared.b16 {%0,%1,%2,%3}, [%4];"
                 : "=r"(r0), "=r"(r1), "=r"(r2), "=r"(r3) : "r"(addr));
}
__device__ __forceinline__ void mma16816(float* d, const uint32_t* a, const uint32_t* b) {
    asm volatile(
        "mma.sync.aligned.m16n8k16.row.col.f32.bf16.bf16.f32 "
        "{%0,%1,%2,%3}, {%4,%5,%6,%7}, {%8,%9}, {%0,%1,%2,%3};"
        : "+f"(d[0]), "+f"(d[1]), "+f"(d[2]), "+f"(d[3])
        : "r"(a[0]), "r"(a[1]), "r"(a[2]), "r"(a[3]), "r"(b[0]), "r"(b[1]));
}
__device__ __forceinline__ uint32_t pack_bf16(float x, float y) {
    __nv_bfloat16 bx = __float2bfloat16(x), by = __float2bfloat16(y);
    return (uint32_t)__bfloat16_as_ushort(bx) | ((uint32_t)__bfloat16_as_ushort(by) << 16);
}

// ---------------------------------------------------------------------------
// Split fp32 -> (bf16 hi, bf16 lo)   (used for raw inputs q,k,v and weights)
// ---------------------------------------------------------------------------
__global__ __launch_bounds__(256) void split_kernel(
    const float* __restrict__ x, __nv_bfloat16* __restrict__ hi,
    __nv_bfloat16* __restrict__ lo, int n)
{
    int i = (blockIdx.x * 256 + threadIdx.x) * 4;
    if (i >= n) return;
    float4 v = *reinterpret_cast<const float4*>(x + i);
    float vs[4] = {v.x, v.y, v.z, v.w};
    uint32_t hp[2], lp[2];
    #pragma unroll
    for (int p = 0; p < 2; p++) {
        __nv_bfloat16 h0 = __float2bfloat16(vs[p * 2 + 0]);
        __nv_bfloat16 h1 = __float2bfloat16(vs[p * 2 + 1]);
        __nv_bfloat16 l0 = __float2bfloat16(vs[p * 2 + 0] - __bfloat162float(h0));
        __nv_bfloat16 l1 = __float2bfloat16(vs[p * 2 + 1] - __bfloat162float(h1));
        hp[p] = (uint32_t)__bfloat16_as_ushort(h0) | ((uint32_t)__bfloat16_as_ushort(h1) << 16);
        lp[p] = (uint32_t)__bfloat16_as_ushort(l0) | ((uint32_t)__bfloat16_as_ushort(l1) << 16);
    }
    *reinterpret_cast<uint2*>(hi + i) = make_uint2(hp[0], hp[1]);
    *reinterpret_cast<uint2*>(lo + i) = make_uint2(lp[0], lp[1]);
}

// ---------------------------------------------------------------------------
// mma.sync GEMM: acc = Ah@Bh^T + Ah@Bl^T + Al@Bh^T; out = acc + bias
// If Yf != null: write fp32. Else: write bf16 split (hi,lo) of (out*scale).
// CTA 128x128, 8 warps 2x4, warp tile 64x32, BK=32, 3-stage cp.async.
// ---------------------------------------------------------------------------
#define BK 32
#define SMEM_STRIDE 80
#define A_STAGE_BYTES (128 * SMEM_STRIDE)
#define STAGE_BYTES (2 * A_STAGE_BYTES)
#define GEMM_SMEM (3 * STAGE_BYTES)
#define CHUNKS_PER_PASS (D_MODEL / BK)
#define NCHUNK (3 * CHUNKS_PER_PASS)

__global__ __launch_bounds__(256) void gemm_mma(
    const __nv_bfloat16* __restrict__ Ah, const __nv_bfloat16* __restrict__ Al,
    const __nv_bfloat16* __restrict__ Bh, const __nv_bfloat16* __restrict__ Bl,
    const float* __restrict__ bias, float* __restrict__ Yf,
    __nv_bfloat16* __restrict__ Yh, __nv_bfloat16* __restrict__ Yl, float scale)
{
    extern __shared__ __align__(128) char smem[];
    const uint32_t sb = smem_to_u32(smem);
    const int t    = threadIdx.x;
    const int wid  = t >> 5;
    const int lane = t & 31;
    const int warp_m = wid & 1;
    const int warp_n = wid >> 1;
    const int n0 = blockIdx.x * 128;
    const int m0 = blockIdx.y * 128;

    const uint32_t a_off = (uint32_t)(warp_m * 64 + (lane & 15)) * SMEM_STRIDE
                         + (uint32_t)(lane >> 4) * 16;
    const uint32_t b_off = (uint32_t)(warp_n * 32 + (lane & 7) + ((lane >> 4) << 3)) * SMEM_STRIDE
                         + (uint32_t)((lane >> 3) & 1) * 16;

    float acc[4][4][4] = {};

    auto load_chunk = [&](int c, int s) {
        const int pass = c / CHUNKS_PER_PASS;
        const int k0 = (c % CHUNKS_PER_PASS) * BK;
        const __nv_bfloat16* a_src = (pass == 2) ? Al : Ah;
        const __nv_bfloat16* b_src = (pass == 1) ? Bl : Bh;
        const uint32_t sA = sb + s * STAGE_BYTES;
        const uint32_t sB = sA + A_STAGE_BYTES;
        #pragma unroll
        for (int i = 0; i < 2; i++) {
            int e = t + i * 256;
            int row = e >> 2, seg = e & 3;
            uint32_t d = (uint32_t)(row * SMEM_STRIDE + seg * 16);
            cp_async16(sA + d, a_src + (size_t)(m0 + row) * D_MODEL + k0 + seg * 8);
            cp_async16(sB + d, b_src + (size_t)(n0 + row) * D_MODEL + k0 + seg * 8);
        }
        cp_commit();
    };

    load_chunk(0, 0);
    load_chunk(1, 1);

    for (int c = 0; c < NCHUNK; c++) {
        if (c + 1 < NCHUNK) cp_wait_group<1>(); else cp_wait_group<0>();
        __syncthreads();
        if (c + 2 < NCHUNK) load_chunk(c + 2, (c + 2) % 3);

        const uint32_t sA = sb + (c % 3) * STAGE_BYTES;
        const uint32_t sB = sA + A_STAGE_BYTES;

        #pragma unroll
        for (int ks = 0; ks < 2; ks++) {
            uint32_t af[4][4];
            #pragma unroll
            for (int mt = 0; mt < 4; mt++)
                ldsm4(af[mt][0], af[mt][1], af[mt][2], af[mt][3],
                      sA + a_off + mt * 16 * SMEM_STRIDE + ks * 32);
            uint32_t bf[4][2];
            #pragma unroll
            for (int p = 0; p < 2; p++) {
                uint32_t r0, r1, r2, r3;
                ldsm4(r0, r1, r2, r3, sB + b_off + p * 16 * SMEM_STRIDE + ks * 32);
                bf[p * 2 + 0][0] = r0; bf[p * 2 + 0][1] = r1;
                bf[p * 2 + 1][0] = r2; bf[p * 2 + 1][1] = r3;
            }
            #pragma unroll
            for (int mt = 0; mt < 4; mt++)
                #pragma unroll
                for (int nt = 0; nt < 4; nt++)
                    mma16816(acc[mt][nt], af[mt], bf[nt]);
        }
        __syncthreads();
    }

    const int colb = n0 + warp_n * 32 + (lane & 3) * 2;
    const int rowb = m0 + warp_m * 64 + (lane >> 2);
    #pragma unroll
    for (int nt = 0; nt < 4; nt++) {
        const int col = colb + nt * 8;
        const float2 bv = *reinterpret_cast<const float2*>(&bias[col]);
        #pragma unroll
        for (int mt = 0; mt < 4; mt++) {
            const int r0 = rowb + mt * 16;
            float o00 = acc[mt][nt][0] + bv.x, o01 = acc[mt][nt][1] + bv.y;
            float o10 = acc[mt][nt][2] + bv.x, o11 = acc[mt][nt][3] + bv.y;
            if (Yf) {
                *reinterpret_cast<float2*>(&Yf[(size_t)r0 * D_MODEL + col]) = make_float2(o00, o01);
                *reinterpret_cast<float2*>(&Yf[(size_t)(r0 + 8) * D_MODEL + col]) = make_float2(o10, o11);
            } else {
                o00 *= scale; o01 *= scale; o10 *= scale; o11 *= scale;
                __nv_bfloat16 h00 = __float2bfloat16(o00), h01 = __float2bfloat16(o01);
                __nv_bfloat16 h10 = __float2bfloat16(o10), h11 = __float2bfloat16(o11);
                uint32_t hp0 = (uint32_t)__bfloat16_as_ushort(h00) | ((uint32_t)__bfloat16_as_ushort(h01) << 16);
                uint32_t hp1 = (uint32_t)__bfloat16_as_ushort(h10) | ((uint32_t)__bfloat16_as_ushort(h11) << 16);
                uint32_t lp0 = pack_bf16(o00 - __bfloat162float(h00), o01 - __bfloat162float(h01));
                uint32_t lp1 = pack_bf16(o10 - __bfloat162float(h10), o11 - __bfloat162float(h11));
                *reinterpret_cast<uint32_t*>(&Yh[(size_t)r0 * D_MODEL + col]) = hp0;
                *reinterpret_cast<uint32_t*>(&Yh[(size_t)(r0 + 8) * D_MODEL + col]) = hp1;
                *reinterpret_cast<uint32_t*>(&Yl[(size_t)r0 * D_MODEL + col]) = lp0;
                *reinterpret_cast<uint32_t*>(&Yl[(size_t)(r0 + 8) * D_MODEL + col]) = lp1;
            }
        }
    }
}

// ---------------------------------------------------------------------------
// FA2-style attention, mma.sync bf16 3-term split.
// CTA: 128 q-rows for one (b,h). 8 warps, warp = 16 rows x full kv chunk.
// kv chunk = 64 keys, 3-stage cp.async. Scale folded into Q split.
// Output: split bf16 ctx written straight into g_xh/g_xl.
// SMEM layout (bytes), row stride 144 (72 bf16):
//  Qh @0 (18432), Ql @18432; stages @36864, each 36864:
//  Kh +0, Kl +9216, Vh +18432, Vl +27648
// ---------------------------------------------------------------------------
#define AT_RS 144
#define AT_Q_BYTES (128 * AT_RS)        // 18432
#define AT_ARR (64 * AT_RS)             // 9216
#define AT_STAGE (4 * AT_ARR)           // 36864
#define AT_KV_BASE (2 * AT_Q_BYTES)     // 36864
#define AT_SMEM (AT_KV_BASE + 3 * AT_STAGE)  // 147456
#define NKV (SEQ / 64)                  // 32

__global__ __launch_bounds__(256, 1) void attn_mma(
    const __nv_bfloat16* __restrict__ qh, const __nv_bfloat16* __restrict__ ql,
    const __nv_bfloat16* __restrict__ kh, const __nv_bfloat16* __restrict__ kl,
    const __nv_bfloat16* __restrict__ vh, const __nv_bfloat16* __restrict__ vl,
    __nv_bfloat16* __restrict__ Ch, __nv_bfloat16* __restrict__ Cl)
{
    extern __shared__ __align__(128) char smem[];
    const uint32_t sb = smem_to_u32(smem);
    const int t    = threadIdx.x;
    const int wid  = t >> 5;
    const int lane = t & 31;
    const int b  = blockIdx.z;
    const int h  = blockIdx.y;
    const int q0 = blockIdx.x * 128;

    const size_t base = (size_t)b * SEQ * D_MODEL + h * D_K;
    const __nv_bfloat16* Qh_g = qh + base + (size_t)q0 * D_MODEL;
    const __nv_bfloat16* Ql_g = ql + base + (size_t)q0 * D_MODEL;
    const __nv_bfloat16* Kh_g = kh + base;
    const __nv_bfloat16* Kl_g = kl + base;
    const __nv_bfloat16* Vh_g = vh + base;
    const __nv_bfloat16* Vl_g = vl + base;

    // Q tiles -> smem (one group)
    #pragma unroll
    for (int i = 0; i < 4; i++) {
        int e = t + i * 256;            // 0..1023
        int row = e >> 3, seg = e & 7;
        uint32_t d = (uint32_t)(row * AT_RS + seg * 16);
        cp_async16(sb + d, Qh_g + (size_t)row * D_MODEL + seg * 8);
        cp_async16(sb + AT_Q_BYTES + d, Ql_g + (size_t)row * D_MODEL + seg * 8);
    }
    cp_commit();

    auto loadkv = [&](int c, int s) {
        const uint32_t st = sb + AT_KV_BASE + s * AT_STAGE;
        #pragma unroll
        for (int i = 0; i < 8; i++) {
            int e = t + i * 256;        // 0..2047
            int arr = e >> 9, row = (e >> 3) & 63, seg = e & 7;
            const __nv_bfloat16* src =
                (arr == 0) ? Kh_g : (arr == 1) ? Kl_g : (arr == 2) ? Vh_g : Vl_g;
            cp_async16(st + arr * AT_ARR + (uint32_t)(row * AT_RS + seg * 16),
                       src + (size_t)(c * 64 + row) * D_MODEL + seg * 8);
        }
        cp_commit();
    };

    loadkv(0, 0);
    loadkv(1, 1);

    // Q fragments -> registers (held whole kernel)
    cp_wait_group<2>();   // Q group done
    __syncthreads();
    uint32_t qfh[4][4], qfl[4][4];
    {
        const uint32_t ab = sb + (uint32_t)(wid * 16 + (lane & 15)) * AT_RS
                          + (uint32_t)(lane >> 4) * 16;
        #pragma unroll
        for (int kk = 0; kk < 4; kk++) {
            ldsm4(qfh[kk][0], qfh[kk][1], qfh[kk][2], qfh[kk][3], ab + kk * 32);
            ldsm4(qfl[kk][0], qfl[kk][1], qfl[kk][2], qfl[kk][3], ab + AT_Q_BYTES + kk * 32);
        }
    }

    float accO[8][4] = {};
    float m0r = -1e30f, m1r = -1e30f, l0 = 0.f, l1 = 0.f;

    const uint32_t bb_off = (uint32_t)((lane & 7) + ((lane >> 4) << 3)) * AT_RS
                          + (uint32_t)((lane >> 3) & 1) * 16;
    const uint32_t vb_off = (uint32_t)(lane & 15) * AT_RS + (uint32_t)(lane >> 4) * 16;

    for (int c = 0; c < NKV; c++) {
        if (c + 1 < NKV) cp_wait_group<1>(); else cp_wait_group<0>();
        __syncthreads();
        if (c + 2 < NKV) loadkv(c + 2, (c + 2) % 3);

        const uint32_t st = sb + AT_KV_BASE + (c % 3) * AT_STAGE;

        // ---- S = Qh*Kh + Ql*Kh + Qh*Kl (scale pre-folded into Q) ----
        float s[8][4] = {};
        #pragma unroll
        for (int kk = 0; kk < 4; kk++) {
            const uint32_t bk = st + bb_off + kk * 32;
            #pragma unroll
            for (int g = 0; g < 4; g++) {
                uint32_t r0, r1, r2, r3;
                ldsm4(r0, r1, r2, r3, bk + (uint32_t)g * 16 * AT_RS);
                uint32_t bh0[2] = {r0, r1}, bh1[2] = {r2, r3};
                mma16816(s[g * 2 + 0], qfh[kk], bh0);
                mma16816(s[g * 2 + 1], qfh[kk], bh1);
                mma16816(s[g * 2 + 0], qfl[kk], bh0);
                mma16816(s[g * 2 + 1], qfl[kk], bh1);
                ldsm4(r0, r1, r2, r3, bk + AT_ARR + (uint32_t)g * 16 * AT_RS);
                uint32_t bl0[2] = {r0, r1}, bl1[2] = {r2, r3};
                mma16816(s[g * 2 + 0], qfh[kk], bl0);
                mma16816(s[g * 2 + 1], qfh[kk], bl1);
            }
        }

        // ---- online softmax (rows: r = lane>>2, r+8) ----
        float mx0 = s[0][0], mx1 = s[0][2];
        #pragma unroll
        for (int j = 0; j < 8; j++) {
            mx0 = fmaxf(mx0, fmaxf(s[j][0], s[j][1]));
            mx1 = fmaxf(mx1, fmaxf(s[j][2], s[j][3]));
        }
        mx0 = fmaxf(mx0, __shfl_xor_sync(0xffffffffu, mx0, 1));
        mx0 = fmaxf(mx0, __shfl_xor_sync(0xffffffffu, mx0, 2));
        mx1 = fmaxf(mx1, __shfl_xor_sync(0xffffffffu, mx1, 1));
        mx1 = fmaxf(mx1, __shfl_xor_sync(0xffffffffu, mx1, 2));

        const float mn0 = fmaxf(m0r, mx0), mn1 = fmaxf(m1r, mx1);
        const float al0 = __expf(m0r - mn0), al1 = __expf(m1r - mn1);
        m0r = mn0; m1r = mn1;

        float rs0 = 0.f, rs1 = 0.f;
        #pragma unroll
        for (int j = 0; j < 8; j++) {
            s[j][0] = __expf(s[j][0] - mn0);
            s[j][1] = __expf(s[j][1] - mn0);
            s[j][2] = __expf(s[j][2] - mn1);
            s[j][3] = __expf(s[j][3] - mn1);
            rs0 += s[j][0] + s[j][1];
            rs1 += s[j][2] + s[j][3];
        }
        rs0 += __shfl_xor_sync(0xffffffffu, rs0, 1);
        rs0 += __shfl_xor_sync(0xffffffffu, rs0, 2);
        rs1 += __shfl_xor_sync(0xffffffffu, rs1, 1);
        rs1 += __shfl_xor_sync(0xffffffffu, rs1, 2);
        l0 = l0 * al0 + rs0;
        l1 = l1 * al1 + rs1;

        #pragma unroll
        for (int nt = 0; nt < 8; nt++) {
            accO[nt][0] *= al0; accO[nt][1] *= al0;
            accO[nt][2] *= al1; accO[nt][3] *= al1;
        }

        // ---- P -> bf16 hi/lo A-fragments (registers only) ----
        uint32_t ph[4][4], pl[4][4];
        #pragma unroll
        for (int kk = 0; kk < 4; kk++) {
            const int j0 = 2 * kk, j1 = 2 * kk + 1;
            float v00 = s[j0][0], v01 = s[j0][1], v02 = s[j0][2], v03 = s[j0][3];
            float v10 = s[j1][0], v11 = s[j1][1], v12 = s[j1][2], v13 = s[j1][3];
            __nv_bfloat16 h;
            float r00, r01, r02, r03, r10, r11, r12, r13;
            h = __float2bfloat16(v00); r00 = v00 - __bfloat162float(h);
            h = __float2bfloat16(v01); r01 = v01 - __bfloat162float(h);
            h = __float2bfloat16(v02); r02 = v02 - __bfloat162float(h);
            h = __float2bfloat16(v03); r03 = v03 - __bfloat162float(h);
            h = __float2bfloat16(v10); r10 = v10 - __bfloat162float(h);
            h = __float2bfloat16(v11); r11 = v11 - __bfloat162float(h);
            h = __float2bfloat16(v12); r12 = v12 - __bfloat162float(h);
            h = __float2bfloat16(v13); r13 = v13 - __bfloat162float(h);
            ph[kk][0] = pack_bf16(v00, v01);
            ph[kk][1] = pack_bf16(v02, v03);
            ph[kk][2] = pack_bf16(v10, v11);
            ph[kk][3] = pack_bf16(v12, v13);
            pl[kk][0] = pack_bf16(r00, r01);
            pl[kk][1] = pack_bf16(r02, r03);
            pl[kk][2] = pack_bf16(r10, r11);
            pl[kk][3] = pack_bf16(r12, r13);
        }

        // ---- O += Ph*Vh + Pl*Vh + Ph*Vl ----
        const uint32_t vst = st + 2 * AT_ARR;
        #pragma unroll
        for (int kk = 0; kk < 4; kk++) {
            const uint32_t vk = vst + vb_off + (uint32_t)(kk * 16) * AT_RS;
            #pragma unroll
            for (int np = 0; np < 4; np++) {
                uint32_t r0, r1, r2, r3;
                ldsm4t(r0, r1, r2, r3, vk + np * 32);
                uint32_t b0[2] = {r0, r1}, b1[2] = {r2, r3};
                mma16816(accO[np * 2 + 0], ph[kk], b0);
                mma16816(accO[np * 2 + 1], ph[kk], b1);
                mma16816(accO[np * 2 + 0], pl[kk], b0);
                mma16816(accO[np * 2 + 1], pl[kk], b1);
                ldsm4t(r0, r1, r2, r3, vk + AT_ARR + np * 32);
                uint32_t c0[2] = {r0, r1}, c1[2] = {r2, r3};
                mma16816(accO[np * 2 + 0], ph[kk], c0);
                mma16816(accO[np * 2 + 1], ph[kk], c1);
            }
        }
    }

    // ---- epilogue: normalize, split to bf16 hi/lo, store ----
    const float inv0 = 1.0f / l0, inv1 = 1.0f / l1;
    const int r0g = q0 + wid * 16 + (lane >> 2);
    const size_t orow0 = ((size_t)b * SEQ + r0g) * D_MODEL + h * D_K;
    const size_t orow1 = orow0 + 8 * D_MODEL;
    #pragma unroll
    for (int nt = 0; nt < 8; nt++) {
        const int col = nt * 8 + (lane & 3) * 2;
        float o00 = accO[nt][0] * inv0, o01 = accO[nt][1] * inv0;
        float o10 = accO[nt][2] * inv1, o11 = accO[nt][3] * inv1;
        __nv_bfloat16 h00 = __float2bfloat16(o00), h01 = __float2bfloat16(o01);
        __nv_bfloat16 h10 = __float2bfloat16(o10), h11 = __float2bfloat16(o11);
        uint32_t hp0 = (uint32_t)__bfloat16_as_ushort(h00) | ((uint32_t)__bfloat16_as_ushort(h01) << 16);
        uint32_t hp1 = (uint32_t)__bfloat16_as_ushort(h10) | ((uint32_t)__bfloat16_as_ushort(h11) << 16);
        uint32_t lp0 = pack_bf16(o00 - __bfloat162float(h00), o01 - __bfloat162float(h01));
        uint32_t lp1 = pack_bf16(o10 - __bfloat162float(h10), o11 - __bfloat162float(h11));
        *reinterpret_cast<uint32_t*>(&Ch[orow0 + col]) = hp0;
        *reinterpret_cast<uint32_t*>(&Ch[orow1 + col]) = hp1;
        *reinterpret_cast<uint32_t*>(&Cl[orow0 + col]) = lp0;
        *reinterpret_cast<uint32_t*>(&Cl[orow1 + col]) = lp1;
    }
}

// ---------------------------------------------------------------------------
// Launch
// ---------------------------------------------------------------------------
extern "C" void kernel_launch(void* const* d_in, const int* in_sizes, int n_in,
                              void* d_out, int out_size)
{
    const float* q   = (const float*)d_in[0];
    const float* k   = (const float*)d_in[1];
    const float* v   = (const float*)d_in[2];
    const float* w_q = (const float*)d_in[3];
    const float* b_q = (const float*)d_in[4];
    const float* w_k = (const float*)d_in[5];
    const float* b_k = (const float*)d_in[6];
    const float* w_v = (const float*)d_in[7];
    const float* b_v = (const float*)d_in[8];
    const float* w_o = (const float*)d_in[9];
    const float* b_o = (const float*)d_in[10];
    float* out = (float*)d_out;

    __nv_bfloat16 *xh, *xl, *wh, *wl, *qh, *ql, *kh, *kl, *vh, *vl;
    cudaGetSymbolAddress((void**)&xh, g_xh);
    cudaGetSymbolAddress((void**)&xl, g_xl);
    cudaGetSymbolAddress((void**)&wh, g_wh);
    cudaGetSymbolAddress((void**)&wl, g_wl);
    cudaGetSymbolAddress((void**)&qh, g_qh);
    cudaGetSymbolAddress((void**)&ql, g_ql);
    cudaGetSymbolAddress((void**)&kh, g_kh);
    cudaGetSymbolAddress((void**)&kl, g_kl);
    cudaGetSymbolAddress((void**)&vh, g_vh);
    cudaGetSymbolAddress((void**)&vl, g_vl);

    cudaFuncSetAttribute(gemm_mma,
                         cudaFuncAttributeMaxDynamicSharedMemorySize, GEMM_SMEM);
    cudaFuncSetAttribute(attn_mma,
                         cudaFuncAttributeMaxDynamicSharedMemorySize, AT_SMEM);

    const int nx = M_ROWS * D_MODEL;
    const int nw = D_MODEL * D_MODEL;
    const int gx = nx / 4 / 256;
    const int gw = nw / 4 / 256;
    dim3 gemm_grid(D_MODEL / 128, M_ROWS / 128);  // (6, 32)

    const float qscale = 0.125f;  // 1/sqrt(64)

    // Q/K/V projections -> split bf16 outputs (scale folded into Q)
    split_kernel<<<gw, 256>>>(w_q, wh, wl, nw);
    split_kernel<<<gx, 256>>>(q, xh, xl, nx);
    gemm_mma<<<gemm_grid, 256, GEMM_SMEM>>>(xh, xl, wh, wl, b_q, nullptr, qh, ql, qscale);

    split_kernel<<<gw, 256>>>(w_k, wh, wl, nw);
    split_kernel<<<gx, 256>>>(k, xh, xl, nx);
    gemm_mma<<<gemm_grid, 256, GEMM_SMEM>>>(xh, xl, wh, wl, b_k, nullptr, kh, kl, 1.0f);

    split_kernel<<<gw, 256>>>(w_v, wh, wl, nw);
    split_kernel<<<gx, 256>>>(v, xh, xl, nx);
    gemm_mma<<<gemm_grid, 256, GEMM_SMEM>>>(xh, xl, wh, wl, b_v, nullptr, vh, vl, 1.0f);

    // Attention (writes split ctx straight into xh/xl)
    dim3 attn_grid(SEQ / 128, NUM_HEADS, BATCH);  // (16, 12, 2)
    attn_mma<<<attn_grid, 256, AT_SMEM>>>(qh, ql, kh, kl, vh, vl, xh, xl);

    // Output projection -> fp32 out
    split_kernel<<<gw, 256>>>(w_o, wh, wl, nw);
    gemm_mma<<<gemm_grid, 256, GEMM_SMEM>>>(xh, xl, wh, wl, b_o, out, nullptr, nullptr, 1.0f);
}

// round 6
// speedup vs baseline: 3.2294x; 1.0005x over previous
#include <cuda_runtime.h>
#include <cuda_bf16.h>
#include <cstdint>

#define D_MODEL 768
#define NUM_HEADS 12
#define D_K 64
#define BATCH 2
#define SEQ 2048
#define M_ROWS (BATCH * SEQ)   // 4096

// ---------------------------------------------------------------------------
// Scratch (__device__ globals; allocation-free rule)
// ---------------------------------------------------------------------------
__device__ __nv_bfloat16 g_xh[M_ROWS * D_MODEL];
__device__ __nv_bfloat16 g_xl[M_ROWS * D_MODEL];
__device__ __nv_bfloat16 g_wh[D_MODEL * D_MODEL];
__device__ __nv_bfloat16 g_wl[D_MODEL * D_MODEL];
__device__ __nv_bfloat16 g_qh[M_ROWS * D_MODEL];
__device__ __nv_bfloat16 g_ql[M_ROWS * D_MODEL];
__device__ __nv_bfloat16 g_kh[M_ROWS * D_MODEL];
__device__ __nv_bfloat16 g_kl[M_ROWS * D_MODEL];
__device__ __nv_bfloat16 g_vh[M_ROWS * D_MODEL];
__device__ __nv_bfloat16 g_vl[M_ROWS * D_MODEL];

// ---------------------------------------------------------------------------
// PTX helpers (family-target safe: cp.async / ldmatrix / mma.sync only)
// ---------------------------------------------------------------------------
__device__ __forceinline__ uint32_t smem_to_u32(const void* p) {
    uint32_t a;
    asm("{ .reg .u64 t; cvta.to.shared.u64 t, %1; cvt.u32.u64 %0, t; }"
        : "=r"(a) : "l"(p));
    return a;
}
__device__ __forceinline__ void cp_async16(uint32_t dst, const void* src) {
    asm volatile("cp.async.cg.shared.global [%0], [%1], 16;" :: "r"(dst), "l"(src));
}
__device__ __forceinline__ void cp_commit() {
    asm volatile("cp.async.commit_group;" ::: "memory");
}
template <int N>
__device__ __forceinline__ void cp_wait_group() {
    asm volatile("cp.async.wait_group %0;" :: "n"(N) : "memory");
}
__device__ __forceinline__ void ldsm4(uint32_t& r0, uint32_t& r1, uint32_t& r2,
                                      uint32_t& r3, uint32_t addr) {
    asm volatile("ldmatrix.sync.aligned.m8n8.x4.shared.b16 {%0,%1,%2,%3}, [%4];"
                 : "=r"(r0), "=r"(r1), "=r"(r2), "=r"(r3) : "r"(addr));
}
__device__ __forceinline__ void ldsm4t(uint32_t& r0, uint32_t& r1, uint32_t& r2,
                                       uint32_t& r3, uint32_t addr) {
    asm volatile("ldmatrix.sync.aligned.m8n8.x4.trans.shared.b16 {%0,%1,%2,%3}, [%4];"
                 : "=r"(r0), "=r"(r1), "=r"(r2), "=r"(r3) : "r"(addr));
}
__device__ __forceinline__ void mma16816(float* d, const uint32_t* a, const uint32_t* b) {
    asm volatile(
        "mma.sync.aligned.m16n8k16.row.col.f32.bf16.bf16.f32 "
        "{%0,%1,%2,%3}, {%4,%5,%6,%7}, {%8,%9}, {%0,%1,%2,%3};"
        : "+f"(d[0]), "+f"(d[1]), "+f"(d[2]), "+f"(d[3])
        : "r"(a[0]), "r"(a[1]), "r"(a[2]), "r"(a[3]), "r"(b[0]), "r"(b[1]));
}
__device__ __forceinline__ uint32_t pack_bf16(float x, float y) {
    __nv_bfloat16 bx = __float2bfloat16(x), by = __float2bfloat16(y);
    return (uint32_t)__bfloat16_as_ushort(bx) | ((uint32_t)__bfloat16_as_ushort(by) << 16);
}

// ---------------------------------------------------------------------------
// Split fp32 -> (bf16 hi, bf16 lo)   (used for raw inputs q,k,v and weights)
// ---------------------------------------------------------------------------
__global__ __launch_bounds__(256) void split_kernel(
    const float* __restrict__ x, __nv_bfloat16* __restrict__ hi,
    __nv_bfloat16* __restrict__ lo, int n)
{
    int i = (blockIdx.x * 256 + threadIdx.x) * 4;
    if (i >= n) return;
    float4 v = *reinterpret_cast<const float4*>(x + i);
    float vs[4] = {v.x, v.y, v.z, v.w};
    uint32_t hp[2], lp[2];
    #pragma unroll
    for (int p = 0; p < 2; p++) {
        __nv_bfloat16 h0 = __float2bfloat16(vs[p * 2 + 0]);
        __nv_bfloat16 h1 = __float2bfloat16(vs[p * 2 + 1]);
        __nv_bfloat16 l0 = __float2bfloat16(vs[p * 2 + 0] - __bfloat162float(h0));
        __nv_bfloat16 l1 = __float2bfloat16(vs[p * 2 + 1] - __bfloat162float(h1));
        hp[p] = (uint32_t)__bfloat16_as_ushort(h0) | ((uint32_t)__bfloat16_as_ushort(h1) << 16);
        lp[p] = (uint32_t)__bfloat16_as_ushort(l0) | ((uint32_t)__bfloat16_as_ushort(l1) << 16);
    }
    *reinterpret_cast<uint2*>(hi + i) = make_uint2(hp[0], hp[1]);
    *reinterpret_cast<uint2*>(lo + i) = make_uint2(lp[0], lp[1]);
}

// ---------------------------------------------------------------------------
// mma.sync GEMM: acc = Ah@Bh^T + Ah@Bl^T + Al@Bh^T; out = acc + bias
// If Yf != null: write fp32. Else: write bf16 split (hi,lo) of (out*scale).
// CTA 128x128, 8 warps 2x4, warp tile 64x32, BK=32, 3-stage cp.async.
// ---------------------------------------------------------------------------
#define BK 32
#define SMEM_STRIDE 80
#define A_STAGE_BYTES (128 * SMEM_STRIDE)
#define STAGE_BYTES (2 * A_STAGE_BYTES)
#define GEMM_SMEM (3 * STAGE_BYTES)
#define CHUNKS_PER_PASS (D_MODEL / BK)
#define NCHUNK (3 * CHUNKS_PER_PASS)

__global__ __launch_bounds__(256) void gemm_mma(
    const __nv_bfloat16* __restrict__ Ah, const __nv_bfloat16* __restrict__ Al,
    const __nv_bfloat16* __restrict__ Bh, const __nv_bfloat16* __restrict__ Bl,
    const float* __restrict__ bias, float* __restrict__ Yf,
    __nv_bfloat16* __restrict__ Yh, __nv_bfloat16* __restrict__ Yl, float scale)
{
    extern __shared__ __align__(128) char smem[];
    const uint32_t sb = smem_to_u32(smem);
    const int t    = threadIdx.x;
    const int wid  = t >> 5;
    const int lane = t & 31;
    const int warp_m = wid & 1;
    const int warp_n = wid >> 1;
    const int n0 = blockIdx.x * 128;
    const int m0 = blockIdx.y * 128;

    const uint32_t a_off = (uint32_t)(warp_m * 64 + (lane & 15)) * SMEM_STRIDE
                         + (uint32_t)(lane >> 4) * 16;
    const uint32_t b_off = (uint32_t)(warp_n * 32 + (lane & 7) + ((lane >> 4) << 3)) * SMEM_STRIDE
                         + (uint32_t)((lane >> 3) & 1) * 16;

    float acc[4][4][4] = {};

    auto load_chunk = [&](int c, int s) {
        const int pass = c / CHUNKS_PER_PASS;
        const int k0 = (c % CHUNKS_PER_PASS) * BK;
        const __nv_bfloat16* a_src = (pass == 2) ? Al : Ah;
        const __nv_bfloat16* b_src = (pass == 1) ? Bl : Bh;
        const uint32_t sA = sb + s * STAGE_BYTES;
        const uint32_t sB = sA + A_STAGE_BYTES;
        #pragma unroll
        for (int i = 0; i < 2; i++) {
            int e = t + i * 256;
            int row = e >> 2, seg = e & 3;
            uint32_t d = (uint32_t)(row * SMEM_STRIDE + seg * 16);
            cp_async16(sA + d, a_src + (size_t)(m0 + row) * D_MODEL + k0 + seg * 8);
            cp_async16(sB + d, b_src + (size_t)(n0 + row) * D_MODEL + k0 + seg * 8);
        }
        cp_commit();
    };

    load_chunk(0, 0);
    load_chunk(1, 1);

    for (int c = 0; c < NCHUNK; c++) {
        if (c + 1 < NCHUNK) cp_wait_group<1>(); else cp_wait_group<0>();
        __syncthreads();
        if (c + 2 < NCHUNK) load_chunk(c + 2, (c + 2) % 3);

        const uint32_t sA = sb + (c % 3) * STAGE_BYTES;
        const uint32_t sB = sA + A_STAGE_BYTES;

        #pragma unroll
        for (int ks = 0; ks < 2; ks++) {
            uint32_t af[4][4];
            #pragma unroll
            for (int mt = 0; mt < 4; mt++)
                ldsm4(af[mt][0], af[mt][1], af[mt][2], af[mt][3],
                      sA + a_off + mt * 16 * SMEM_STRIDE + ks * 32);
            uint32_t bf[4][2];
            #pragma unroll
            for (int p = 0; p < 2; p++) {
                uint32_t r0, r1, r2, r3;
                ldsm4(r0, r1, r2, r3, sB + b_off + p * 16 * SMEM_STRIDE + ks * 32);
                bf[p * 2 + 0][0] = r0; bf[p * 2 + 0][1] = r1;
                bf[p * 2 + 1][0] = r2; bf[p * 2 + 1][1] = r3;
            }
            #pragma unroll
            for (int mt = 0; mt < 4; mt++)
                #pragma unroll
                for (int nt = 0; nt < 4; nt++)
                    mma16816(acc[mt][nt], af[mt], bf[nt]);
        }
        __syncthreads();
    }

    const int colb = n0 + warp_n * 32 + (lane & 3) * 2;
    const int rowb = m0 + warp_m * 64 + (lane >> 2);
    #pragma unroll
    for (int nt = 0; nt < 4; nt++) {
        const int col = colb + nt * 8;
        const float2 bv = *reinterpret_cast<const float2*>(&bias[col]);
        #pragma unroll
        for (int mt = 0; mt < 4; mt++) {
            const int r0 = rowb + mt * 16;
            float o00 = acc[mt][nt][0] + bv.x, o01 = acc[mt][nt][1] + bv.y;
            float o10 = acc[mt][nt][2] + bv.x, o11 = acc[mt][nt][3] + bv.y;
            if (Yf) {
                *reinterpret_cast<float2*>(&Yf[(size_t)r0 * D_MODEL + col]) = make_float2(o00, o01);
                *reinterpret_cast<float2*>(&Yf[(size_t)(r0 + 8) * D_MODEL + col]) = make_float2(o10, o11);
            } else {
                o00 *= scale; o01 *= scale; o10 *= scale; o11 *= scale;
                __nv_bfloat16 h00 = __float2bfloat16(o00), h01 = __float2bfloat16(o01);
                __nv_bfloat16 h10 = __float2bfloat16(o10), h11 = __float2bfloat16(o11);
                uint32_t hp0 = (uint32_t)__bfloat16_as_ushort(h00) | ((uint32_t)__bfloat16_as_ushort(h01) << 16);
                uint32_t hp1 = (uint32_t)__bfloat16_as_ushort(h10) | ((uint32_t)__bfloat16_as_ushort(h11) << 16);
                uint32_t lp0 = pack_bf16(o00 - __bfloat162float(h00), o01 - __bfloat162float(h01));
                uint32_t lp1 = pack_bf16(o10 - __bfloat162float(h10), o11 - __bfloat162float(h11));
                *reinterpret_cast<uint32_t*>(&Yh[(size_t)r0 * D_MODEL + col]) = hp0;
                *reinterpret_cast<uint32_t*>(&Yh[(size_t)(r0 + 8) * D_MODEL + col]) = hp1;
                *reinterpret_cast<uint32_t*>(&Yl[(size_t)r0 * D_MODEL + col]) = lp0;
                *reinterpret_cast<uint32_t*>(&Yl[(size_t)(r0 + 8) * D_MODEL + col]) = lp1;
            }
        }
    }
}

// ---------------------------------------------------------------------------
// FA2-style attention, mma.sync bf16 3-term split.
// CTA: 128 q-rows for one (b,h). 8 warps, warp = 16 rows x full kv chunk.
// kv chunk = 64 keys, 3-stage cp.async. Scale folded into Q split.
// Output: split bf16 ctx written straight into g_xh/g_xl.
// SMEM layout (bytes), row stride 144 (72 bf16):
//  Qh @0 (18432), Ql @18432; stages @36864, each 36864:
//  Kh +0, Kl +9216, Vh +18432, Vl +27648
// ---------------------------------------------------------------------------
#define AT_RS 144
#define AT_Q_BYTES (128 * AT_RS)        // 18432
#define AT_ARR (64 * AT_RS)             // 9216
#define AT_STAGE (4 * AT_ARR)           // 36864
#define AT_KV_BASE (2 * AT_Q_BYTES)     // 36864
#define AT_SMEM (AT_KV_BASE + 3 * AT_STAGE)  // 147456
#define NKV (SEQ / 64)                  // 32

__global__ __launch_bounds__(256, 1) void attn_mma(
    const __nv_bfloat16* __restrict__ qh, const __nv_bfloat16* __restrict__ ql,
    const __nv_bfloat16* __restrict__ kh, const __nv_bfloat16* __restrict__ kl,
    const __nv_bfloat16* __restrict__ vh, const __nv_bfloat16* __restrict__ vl,
    __nv_bfloat16* __restrict__ Ch, __nv_bfloat16* __restrict__ Cl)
{
    extern __shared__ __align__(128) char smem[];
    const uint32_t sb = smem_to_u32(smem);
    const int t    = threadIdx.x;
    const int wid  = t >> 5;
    const int lane = t & 31;
    const int b  = blockIdx.z;
    const int h  = blockIdx.y;
    const int q0 = blockIdx.x * 128;

    const size_t base = (size_t)b * SEQ * D_MODEL + h * D_K;
    const __nv_bfloat16* Qh_g = qh + base + (size_t)q0 * D_MODEL;
    const __nv_bfloat16* Ql_g = ql + base + (size_t)q0 * D_MODEL;
    const __nv_bfloat16* Kh_g = kh + base;
    const __nv_bfloat16* Kl_g = kl + base;
    const __nv_bfloat16* Vh_g = vh + base;
    const __nv_bfloat16* Vl_g = vl + base;

    // Q tiles -> smem (one group)
    #pragma unroll
    for (int i = 0; i < 4; i++) {
        int e = t + i * 256;            // 0..1023
        int row = e >> 3, seg = e & 7;
        uint32_t d = (uint32_t)(row * AT_RS + seg * 16);
        cp_async16(sb + d, Qh_g + (size_t)row * D_MODEL + seg * 8);
        cp_async16(sb + AT_Q_BYTES + d, Ql_g + (size_t)row * D_MODEL + seg * 8);
    }
    cp_commit();

    auto loadkv = [&](int c, int s) {
        const uint32_t st = sb + AT_KV_BASE + s * AT_STAGE;
        #pragma unroll
        for (int i = 0; i < 8; i++) {
            int e = t + i * 256;        // 0..2047
            int arr = e >> 9, row = (e >> 3) & 63, seg = e & 7;
            const __nv_bfloat16* src =
                (arr == 0) ? Kh_g : (arr == 1) ? Kl_g : (arr == 2) ? Vh_g : Vl_g;
            cp_async16(st + arr * AT_ARR + (uint32_t)(row * AT_RS + seg * 16),
                       src + (size_t)(c * 64 + row) * D_MODEL + seg * 8);
        }
        cp_commit();
    };

    loadkv(0, 0);
    loadkv(1, 1);

    // Q fragments -> registers (held whole kernel)
    cp_wait_group<2>();   // Q group done
    __syncthreads();
    uint32_t qfh[4][4], qfl[4][4];
    {
        const uint32_t ab = sb + (uint32_t)(wid * 16 + (lane & 15)) * AT_RS
                          + (uint32_t)(lane >> 4) * 16;
        #pragma unroll
        for (int kk = 0; kk < 4; kk++) {
            ldsm4(qfh[kk][0], qfh[kk][1], qfh[kk][2], qfh[kk][3], ab + kk * 32);
            ldsm4(qfl[kk][0], qfl[kk][1], qfl[kk][2], qfl[kk][3], ab + AT_Q_BYTES + kk * 32);
        }
    }

    float accO[8][4] = {};
    float m0r = -1e30f, m1r = -1e30f, l0 = 0.f, l1 = 0.f;

    const uint32_t bb_off = (uint32_t)((lane & 7) + ((lane >> 4) << 3)) * AT_RS
                          + (uint32_t)((lane >> 3) & 1) * 16;
    const uint32_t vb_off = (uint32_t)(lane & 15) * AT_RS + (uint32_t)(lane >> 4) * 16;

    for (int c = 0; c < NKV; c++) {
        if (c + 1 < NKV) cp_wait_group<1>(); else cp_wait_group<0>();
        __syncthreads();
        if (c + 2 < NKV) loadkv(c + 2, (c + 2) % 3);

        const uint32_t st = sb + AT_KV_BASE + (c % 3) * AT_STAGE;

        // ---- S = Qh*Kh + Ql*Kh + Qh*Kl (scale pre-folded into Q) ----
        float s[8][4] = {};
        #pragma unroll
        for (int kk = 0; kk < 4; kk++) {
            const uint32_t bk = st + bb_off + kk * 32;
            #pragma unroll
            for (int g = 0; g < 4; g++) {
                uint32_t r0, r1, r2, r3;
                ldsm4(r0, r1, r2, r3, bk + (uint32_t)g * 16 * AT_RS);
                uint32_t bh0[2] = {r0, r1}, bh1[2] = {r2, r3};
                mma16816(s[g * 2 + 0], qfh[kk], bh0);
                mma16816(s[g * 2 + 1], qfh[kk], bh1);
                mma16816(s[g * 2 + 0], qfl[kk], bh0);
                mma16816(s[g * 2 + 1], qfl[kk], bh1);
                ldsm4(r0, r1, r2, r3, bk + AT_ARR + (uint32_t)g * 16 * AT_RS);
                uint32_t bl0[2] = {r0, r1}, bl1[2] = {r2, r3};
                mma16816(s[g * 2 + 0], qfh[kk], bl0);
                mma16816(s[g * 2 + 1], qfh[kk], bl1);
            }
        }

        // ---- online softmax (rows: r = lane>>2, r+8) ----
        float mx0 = s[0][0], mx1 = s[0][2];
        #pragma unroll
        for (int j = 0; j < 8; j++) {
            mx0 = fmaxf(mx0, fmaxf(s[j][0], s[j][1]));
            mx1 = fmaxf(mx1, fmaxf(s[j][2], s[j][3]));
        }
        mx0 = fmaxf(mx0, __shfl_xor_sync(0xffffffffu, mx0, 1));
        mx0 = fmaxf(mx0, __shfl_xor_sync(0xffffffffu, mx0, 2));
        mx1 = fmaxf(mx1, __shfl_xor_sync(0xffffffffu, mx1, 1));
        mx1 = fmaxf(mx1, __shfl_xor_sync(0xffffffffu, mx1, 2));

        const float mn0 = fmaxf(m0r, mx0), mn1 = fmaxf(m1r, mx1);
        const float al0 = __expf(m0r - mn0), al1 = __expf(m1r - mn1);
        m0r = mn0; m1r = mn1;

        float rs0 = 0.f, rs1 = 0.f;
        #pragma unroll
        for (int j = 0; j < 8; j++) {
            s[j][0] = __expf(s[j][0] - mn0);
            s[j][1] = __expf(s[j][1] - mn0);
            s[j][2] = __expf(s[j][2] - mn1);
            s[j][3] = __expf(s[j][3] - mn1);
            rs0 += s[j][0] + s[j][1];
            rs1 += s[j][2] + s[j][3];
        }
        rs0 += __shfl_xor_sync(0xffffffffu, rs0, 1);
        rs0 += __shfl_xor_sync(0xffffffffu, rs0, 2);
        rs1 += __shfl_xor_sync(0xffffffffu, rs1, 1);
        rs1 += __shfl_xor_sync(0xffffffffu, rs1, 2);
        l0 = l0 * al0 + rs0;
        l1 = l1 * al1 + rs1;

        #pragma unroll
        for (int nt = 0; nt < 8; nt++) {
            accO[nt][0] *= al0; accO[nt][1] *= al0;
            accO[nt][2] *= al1; accO[nt][3] *= al1;
        }

        // ---- P -> bf16 hi/lo A-fragments (registers only) ----
        uint32_t ph[4][4], pl[4][4];
        #pragma unroll
        for (int kk = 0; kk < 4; kk++) {
            const int j0 = 2 * kk, j1 = 2 * kk + 1;
            float v00 = s[j0][0], v01 = s[j0][1], v02 = s[j0][2], v03 = s[j0][3];
            float v10 = s[j1][0], v11 = s[j1][1], v12 = s[j1][2], v13 = s[j1][3];
            __nv_bfloat16 h;
            float r00, r01, r02, r03, r10, r11, r12, r13;
            h = __float2bfloat16(v00); r00 = v00 - __bfloat162float(h);
            h = __float2bfloat16(v01); r01 = v01 - __bfloat162float(h);
            h = __float2bfloat16(v02); r02 = v02 - __bfloat162float(h);
            h = __float2bfloat16(v03); r03 = v03 - __bfloat162float(h);
            h = __float2bfloat16(v10); r10 = v10 - __bfloat162float(h);
            h = __float2bfloat16(v11); r11 = v11 - __bfloat162float(h);
            h = __float2bfloat16(v12); r12 = v12 - __bfloat162float(h);
            h = __float2bfloat16(v13); r13 = v13 - __bfloat162float(h);
            ph[kk][0] = pack_bf16(v00, v01);
            ph[kk][1] = pack_bf16(v02, v03);
            ph[kk][2] = pack_bf16(v10, v11);
            ph[kk][3] = pack_bf16(v12, v13);
            pl[kk][0] = pack_bf16(r00, r01);
            pl[kk][1] = pack_bf16(r02, r03);
            pl[kk][2] = pack_bf16(r10, r11);
            pl[kk][3] = pack_bf16(r12, r13);
        }

        // ---- O += Ph*Vh + Pl*Vh + Ph*Vl ----
        const uint32_t vst = st + 2 * AT_ARR;
        #pragma unroll
        for (int kk = 0; kk < 4; kk++) {
            const uint32_t vk = vst + vb_off + (uint32_t)(kk * 16) * AT_RS;
            #pragma unroll
            for (int np = 0; np < 4; np++) {
                uint32_t r0, r1, r2, r3;
                ldsm4t(r0, r1, r2, r3, vk + np * 32);
                uint32_t b0[2] = {r0, r1}, b1[2] = {r2, r3};
                mma16816(accO[np * 2 + 0], ph[kk], b0);
                mma16816(accO[np * 2 + 1], ph[kk], b1);
                mma16816(accO[np * 2 + 0], pl[kk], b0);
                mma16816(accO[np * 2 + 1], pl[kk], b1);
                ldsm4t(r0, r1, r2, r3, vk + AT_ARR + np * 32);
                uint32_t c0[2] = {r0, r1}, c1[2] = {r2, r3};
                mma16816(accO[np * 2 + 0], ph[kk], c0);
                mma16816(accO[np * 2 + 1], ph[kk], c1);
            }
        }
    }

    // ---- epilogue: normalize, split to bf16 hi/lo, store ----
    const float inv0 = 1.0f / l0, inv1 = 1.0f / l1;
    const int r0g = q0 + wid * 16 + (lane >> 2);
    const size_t orow0 = ((size_t)b * SEQ + r0g) * D_MODEL + h * D_K;
    const size_t orow1 = orow0 + 8 * D_MODEL;
    #pragma unroll
    for (int nt = 0; nt < 8; nt++) {
        const int col = nt * 8 + (lane & 3) * 2;
        float o00 = accO[nt][0] * inv0, o01 = accO[nt][1] * inv0;
        float o10 = accO[nt][2] * inv1, o11 = accO[nt][3] * inv1;
        __nv_bfloat16 h00 = __float2bfloat16(o00), h01 = __float2bfloat16(o01);
        __nv_bfloat16 h10 = __float2bfloat16(o10), h11 = __float2bfloat16(o11);
        uint32_t hp0 = (uint32_t)__bfloat16_as_ushort(h00) | ((uint32_t)__bfloat16_as_ushort(h01) << 16);
        uint32_t hp1 = (uint32_t)__bfloat16_as_ushort(h10) | ((uint32_t)__bfloat16_as_ushort(h11) << 16);
        uint32_t lp0 = pack_bf16(o00 - __bfloat162float(h00), o01 - __bfloat162float(h01));
        uint32_t lp1 = pack_bf16(o10 - __bfloat162float(h10), o11 - __bfloat162float(h11));
        *reinterpret_cast<uint32_t*>(&Ch[orow0 + col]) = hp0;
        *reinterpret_cast<uint32_t*>(&Ch[orow1 + col]) = hp1;
        *reinterpret_cast<uint32_t*>(&Cl[orow0 + col]) = lp0;
        *reinterpret_cast<uint32_t*>(&Cl[orow1 + col]) = lp1;
    }
}

// ---------------------------------------------------------------------------
// Launch
// ---------------------------------------------------------------------------
extern "C" void kernel_launch(void* const* d_in, const int* in_sizes, int n_in,
                              void* d_out, int out_size)
{
    const float* q   = (const float*)d_in[0];
    const float* k   = (const float*)d_in[1];
    const float* v   = (const float*)d_in[2];
    const float* w_q = (const float*)d_in[3];
    const float* b_q = (const float*)d_in[4];
    const float* w_k = (const float*)d_in[5];
    const float* b_k = (const float*)d_in[6];
    const float* w_v = (const float*)d_in[7];
    const float* b_v = (const float*)d_in[8];
    const float* w_o = (const float*)d_in[9];
    const float* b_o = (const float*)d_in[10];
    float* out = (float*)d_out;

    __nv_bfloat16 *xh, *xl, *wh, *wl, *qh, *ql, *kh, *kl, *vh, *vl;
    cudaGetSymbolAddress((void**)&xh, g_xh);
    cudaGetSymbolAddress((void**)&xl, g_xl);
    cudaGetSymbolAddress((void**)&wh, g_wh);
    cudaGetSymbolAddress((void**)&wl, g_wl);
    cudaGetSymbolAddress((void**)&qh, g_qh);
    cudaGetSymbolAddress((void**)&ql, g_ql);
    cudaGetSymbolAddress((void**)&kh, g_kh);
    cudaGetSymbolAddress((void**)&kl, g_kl);
    cudaGetSymbolAddress((void**)&vh, g_vh);
    cudaGetSymbolAddress((void**)&vl, g_vl);

    cudaFuncSetAttribute(gemm_mma,
                         cudaFuncAttributeMaxDynamicSharedMemorySize, GEMM_SMEM);
    cudaFuncSetAttribute(attn_mma,
                         cudaFuncAttributeMaxDynamicSharedMemorySize, AT_SMEM);

    const int nx = M_ROWS * D_MODEL;
    const int nw = D_MODEL * D_MODEL;
    const int gx = nx / 4 / 256;
    const int gw = nw / 4 / 256;
    dim3 gemm_grid(D_MODEL / 128, M_ROWS / 128);  // (6, 32)

    const float qscale = 0.125f;  // 1/sqrt(64)

    // Q/K/V projections -> split bf16 outputs (scale folded into Q)
    split_kernel<<<gw, 256>>>(w_q, wh, wl, nw);
    split_kernel<<<gx, 256>>>(q, xh, xl, nx);
    gemm_mma<<<gemm_grid, 256, GEMM_SMEM>>>(xh, xl, wh, wl, b_q, nullptr, qh, ql, qscale);

    split_kernel<<<gw, 256>>>(w_k, wh, wl, nw);
    split_kernel<<<gx, 256>>>(k, xh, xl, nx);
    gemm_mma<<<gemm_grid, 256, GEMM_SMEM>>>(xh, xl, wh, wl, b_k, nullptr, kh, kl, 1.0f);

    split_kernel<<<gw, 256>>>(w_v, wh, wl, nw);
    split_kernel<<<gx, 256>>>(v, xh, xl, nx);
    gemm_mma<<<gemm_grid, 256, GEMM_SMEM>>>(xh, xl, wh, wl, b_v, nullptr, vh, vl, 1.0f);

    // Attention (writes split ctx straight into xh/xl)
    dim3 attn_grid(SEQ / 128, NUM_HEADS, BATCH);  // (16, 12, 2)
    attn_mma<<<attn_grid, 256, AT_SMEM>>>(qh, ql, kh, kl, vh, vl, xh, xl);

    // Output projection -> fp32 out
    split_kernel<<<gw, 256>>>(w_o, wh, wl, nw);
    gemm_mma<<<gemm_grid, 256, GEMM_SMEM>>>(xh, xl, wh, wl, b_o, out, nullptr, nullptr, 1.0f);
}